// round 2
// baseline (speedup 1.0000x reference)
#include <cuda_runtime.h>
#include <math.h>

#define Bz 128
#define Lz 1024
#define Dz 256
#define Tz 32
#define BD (Bz*Dz)      /* 32768  */
#define BL (Bz*Lz)      /* 131072 */

// ---------------- scratch (device globals; no allocation) ----------------
__device__ float g_hr[2*BD];
__device__ float g_hw[2*BD];
__device__ float g_cr[BD];
__device__ float g_cw[BD];
__device__ float g_m[BD];
__device__ float g_logits[BD];
__device__ float g_z[BL];

// ---------------- reduction helpers ----------------
__device__ __forceinline__ float warp_sum(float v){
#pragma unroll
  for (int o=16;o;o>>=1) v += __shfl_xor_sync(0xffffffffu,v,o);
  return v;
}
__device__ __forceinline__ float warp_max(float v){
#pragma unroll
  for (int o=16;o;o>>=1) v = fmaxf(v, __shfl_xor_sync(0xffffffffu,v,o));
  return v;
}
// 256-thread block reductions; sbuf must hold >= 8 floats
__device__ __forceinline__ float block_sum(float v, float* sbuf){
  v = warp_sum(v);
  int lane = threadIdx.x & 31, w = threadIdx.x >> 5;
  __syncthreads();
  if (lane == 0) sbuf[w] = v;
  __syncthreads();
  float r = sbuf[0];
#pragma unroll
  for (int i=1;i<8;i++) r += sbuf[i];
  return r;
}
__device__ __forceinline__ float block_max(float v, float* sbuf){
  v = warp_max(v);
  int lane = threadIdx.x & 31, w = threadIdx.x >> 5;
  __syncthreads();
  if (lane == 0) sbuf[w] = v;
  __syncthreads();
  float r = sbuf[0];
#pragma unroll
  for (int i=1;i<8;i++) r = fmaxf(r, sbuf[i]);
  return r;
}

// ---------------- fused LSTM cell: gates GEMM + pointwise ----------------
// g[b,j] = sum_k x[b,k] Wih[j,k] + sum_k h[b,k] Whh[j,k] + bih[j] + bhh[j]
// tile: 16 b-rows x 16 d-cols x 4 gates per CTA. grid (16 dblk, 8 bblk) = 128 CTAs.
// if softmax_x: softmax the x rows first (write-LSTM input is softmax(logits)).
__global__ __launch_bounds__(256,1) void lstm_kernel(
  const float* __restrict__ x, const float* __restrict__ h_in,
  const float* __restrict__ Wih, const float* __restrict__ Whh,
  const float* __restrict__ bih, const float* __restrict__ bhh,
  const float* __restrict__ c_in, float* __restrict__ h_out,
  float* __restrict__ c_out, float* __restrict__ out_copy, int softmax_x)
{
  __shared__ __align__(16) float sA[16*516];   // [bi][k], k in [0,512), stride 516
  __shared__ __align__(16) float sW[64*36];    // [g*16+dd][kk], stride 36
  __shared__ float sred[16*17];
  __shared__ float srow[16];

  const int tid = threadIdx.x;
  const int bi = tid & 15, di = tid >> 4;
  const int b0 = blockIdx.y << 4;
  const int d0 = blockIdx.x << 4;

  // stage A = [x | h_in] rows
  for (int idx = tid; idx < 4096; idx += 256) {
    int bb = idx >> 8, k = idx & 255;
    sA[bb*516 + k]       = x[(b0+bb)*Dz + k];
    sA[bb*516 + 256 + k] = h_in[(b0+bb)*Dz + k];
  }
  __syncthreads();

  if (softmax_x) {
    float lmax = -INFINITY;
    for (int k = di; k < 256; k += 16) lmax = fmaxf(lmax, sA[bi*516+k]);
    sred[bi*17+di] = lmax;
    __syncthreads();
    if (di == 0) { float mm=-INFINITY; for (int j=0;j<16;j++) mm=fmaxf(mm,sred[bi*17+j]); srow[bi]=mm; }
    __syncthreads();
    float rmax = srow[bi];
    float lsum = 0.f;
    for (int k = di; k < 256; k += 16) { float e = expf(sA[bi*516+k]-rmax); sA[bi*516+k]=e; lsum+=e; }
    __syncthreads();
    sred[bi*17+di] = lsum;
    __syncthreads();
    if (di == 0) { float s=0.f; for (int j=0;j<16;j++) s+=sred[bi*17+j]; srow[bi]=1.f/s; }
    __syncthreads();
    float inv = srow[bi];
    for (int k = di; k < 256; k += 16) sA[bi*516+k] *= inv;
  }

  float acc0=0.f, acc1=0.f, acc2=0.f, acc3=0.f;
  for (int kt = 0; kt < 16; kt++) {
    __syncthreads();
    const int k0 = kt << 5;
    const float* Wsrc = (k0 < 256) ? Wih : Whh;
    const int kw = k0 & 255;
    for (int idx = tid; idx < 2048; idx += 256) {
      int rl = idx >> 5, kk = idx & 31;
      int g = rl >> 4, dd = rl & 15;
      sW[rl*36 + kk] = Wsrc[(g*256 + d0 + dd)*256 + kw + kk];
    }
    __syncthreads();
#pragma unroll
    for (int kk = 0; kk < 32; kk += 4) {
      float4 a  = *(const float4*)&sA[bi*516 + k0 + kk];
      float4 w0 = *(const float4*)&sW[(     di)*36 + kk];
      float4 w1 = *(const float4*)&sW[(16 + di)*36 + kk];
      float4 w2 = *(const float4*)&sW[(32 + di)*36 + kk];
      float4 w3 = *(const float4*)&sW[(48 + di)*36 + kk];
      acc0 = fmaf(a.x,w0.x,acc0); acc0 = fmaf(a.y,w0.y,acc0); acc0 = fmaf(a.z,w0.z,acc0); acc0 = fmaf(a.w,w0.w,acc0);
      acc1 = fmaf(a.x,w1.x,acc1); acc1 = fmaf(a.y,w1.y,acc1); acc1 = fmaf(a.z,w1.z,acc1); acc1 = fmaf(a.w,w1.w,acc1);
      acc2 = fmaf(a.x,w2.x,acc2); acc2 = fmaf(a.y,w2.y,acc2); acc2 = fmaf(a.z,w2.z,acc2); acc2 = fmaf(a.w,w2.w,acc2);
      acc3 = fmaf(a.x,w3.x,acc3); acc3 = fmaf(a.y,w3.y,acc3); acc3 = fmaf(a.z,w3.z,acc3); acc3 = fmaf(a.w,w3.w,acc3);
    }
  }

  const int b = b0 + bi, d = d0 + di;
  const int j = d0 + di;
  acc0 += bih[j]       + bhh[j];
  acc1 += bih[256 + j] + bhh[256 + j];
  acc2 += bih[512 + j] + bhh[512 + j];
  acc3 += bih[768 + j] + bhh[768 + j];
  float ig = 1.f/(1.f+expf(-acc0));
  float fg = 1.f/(1.f+expf(-acc1));
  float gg = tanhf(acc2);
  float og = 1.f/(1.f+expf(-acc3));
  float c2 = fmaf(fg, c_in[b*Dz+d], ig*gg);
  float hv = og * tanhf(c2);
  c_out[b*Dz+d] = c2;
  h_out[b*Dz+d] = hv;
  if (out_copy) out_copy[b*Dz+d] = hv;
}

// ---------------- comp logits GEMM: [hr|m] @ Wc^T + bc ----------------
// tile 16b x 32 cols, 2 cols/thread. grid (8 colblk, 8 bblk) = 64 CTAs.
__global__ __launch_bounds__(256,1) void comp_gemm(
  const float* __restrict__ hr, const float* __restrict__ m,
  const float* __restrict__ Wc, const float* __restrict__ bc,
  float* __restrict__ logits)
{
  __shared__ __align__(16) float sA[16*516];
  __shared__ __align__(16) float sW[32*36];
  const int tid = threadIdx.x;
  const int bi = tid & 15, ci = tid >> 4;   // ci in [0,16), 2 cols each
  const int b0 = blockIdx.y << 4;
  const int c0 = blockIdx.x << 5;

  for (int idx = tid; idx < 4096; idx += 256) {
    int bb = idx >> 8, k = idx & 255;
    sA[bb*516 + k]       = hr[(b0+bb)*Dz + k];
    sA[bb*516 + 256 + k] = m[(b0+bb)*Dz + k];
  }

  float acc0=0.f, acc1=0.f;
  for (int kt = 0; kt < 16; kt++) {
    __syncthreads();
    const int k0 = kt << 5;
    for (int idx = tid; idx < 1024; idx += 256) {
      int rl = idx >> 5, kk = idx & 31;
      sW[rl*36 + kk] = Wc[(c0+rl)*512 + k0 + kk];
    }
    __syncthreads();
#pragma unroll
    for (int kk = 0; kk < 32; kk += 4) {
      float4 a  = *(const float4*)&sA[bi*516 + k0 + kk];
      float4 w0 = *(const float4*)&sW[(ci*2    )*36 + kk];
      float4 w1 = *(const float4*)&sW[(ci*2 + 1)*36 + kk];
      acc0 = fmaf(a.x,w0.x,acc0); acc0 = fmaf(a.y,w0.y,acc0); acc0 = fmaf(a.z,w0.z,acc0); acc0 = fmaf(a.w,w0.w,acc0);
      acc1 = fmaf(a.x,w1.x,acc1); acc1 = fmaf(a.y,w1.y,acc1); acc1 = fmaf(a.z,w1.z,acc1); acc1 = fmaf(a.w,w1.w,acc1);
    }
  }
  const int b = b0 + bi;
  const int j0 = c0 + ci*2;
  logits[b*Dz + j0]     = acc0 + bc[j0];
  logits[b*Dz + j0 + 1] = acc1 + bc[j0 + 1];
}

// ---------------- t=0 attention: z_raw = hr . M[b,l,:] ----------------
__global__ __launch_bounds__(256,1) void attn0_raw(
  const float* __restrict__ hr, const float* __restrict__ M, float* __restrict__ z)
{
  __shared__ float shr[256];
  const int b = blockIdx.y;
  const int l0 = blockIdx.x << 7;
  const int tid = threadIdx.x;
  shr[tid] = hr[b*Dz + tid];
  __syncthreads();
  const int warp = tid >> 5, lane = tid & 31;
  for (int l = l0 + warp; l < l0 + 128; l += 8) {
    const float* Mr = M + ((size_t)b*Lz + l)*Dz;
    float s = 0.f;
#pragma unroll
    for (int u = 0; u < 8; u++) { int k = lane + (u << 5); s = fmaf(Mr[k], shr[k], s); }
    s = warp_sum(s);
    if (lane == 0) z[b*Lz + l] = s;
  }
}

// ---------------- t=0: masked softmax over L, then m = z @ M[b] ----------------
__global__ __launch_bounds__(256,1) void attn0_m(
  const float* __restrict__ M, const int* __restrict__ mask,
  float* __restrict__ z, float* __restrict__ m_out)
{
  __shared__ float sz[1024];
  __shared__ float sbuf[8];
  const int b = blockIdx.x, tid = threadIdx.x;
  float raw[4]; float lmax = -INFINITY;
#pragma unroll
  for (int u = 0; u < 4; u++) {
    int l = tid + (u << 8);
    raw[u] = mask[b*Lz + l] ? -INFINITY : z[b*Lz + l];
    lmax = fmaxf(lmax, raw[u]);
  }
  float gmax = block_max(lmax, sbuf);
  float e[4]; float lsum = 0.f;
#pragma unroll
  for (int u = 0; u < 4; u++) { e[u] = expf(raw[u] - gmax); lsum += e[u]; }
  float gsum = block_sum(lsum, sbuf);
  float inv = 1.f / gsum;
#pragma unroll
  for (int u = 0; u < 4; u++) { int l = tid + (u << 8); float zn = e[u]*inv; sz[l] = zn; z[b*Lz + l] = zn; }
  __syncthreads();
  const float* Mb = M + (size_t)b*Lz*Dz + tid;
  float a0=0.f,a1=0.f,a2=0.f,a3=0.f;
#pragma unroll 4
  for (int l = 0; l < Lz; l += 4) {
    a0 = fmaf(sz[l+0], Mb[(size_t)(l+0)*Dz], a0);
    a1 = fmaf(sz[l+1], Mb[(size_t)(l+1)*Dz], a1);
    a2 = fmaf(sz[l+2], Mb[(size_t)(l+2)*Dz], a2);
    a3 = fmaf(sz[l+3], Mb[(size_t)(l+3)*Dz], a3);
  }
  m_out[b*Dz + tid] = (a0 + a1) + (a2 + a3);
}

// ---------------- t>=1 attention via rank-1 structure of M ----------------
// M_prev[b,l,d] = (1 - zp[b,l]) + hw_prev[b,d]*zp[b,l]
// z_raw = Shr + zp*(hr.hw_prev - Shr);  m = (1-S) + hw_prev*S, S = sum z_new*zp
__global__ __launch_bounds__(256,1) void attn_step(
  const float* __restrict__ hr, const float* __restrict__ hw_prev,
  const int* __restrict__ mask, float* __restrict__ z, float* __restrict__ m_out)
{
  __shared__ float sbuf[8];
  const int b = blockIdx.x, tid = threadIdx.x;
  float hrv = hr[b*Dz + tid];
  float hwv = hw_prev[b*Dz + tid];
  float Shr  = block_sum(hrv, sbuf);
  __syncthreads();
  float dotv = block_sum(hrv*hwv, sbuf);
  float alpha = dotv - Shr;
  float zp[4], raw[4]; float lmax = -INFINITY;
#pragma unroll
  for (int u = 0; u < 4; u++) {
    int l = tid + (u << 8);
    zp[u] = z[b*Lz + l];
    raw[u] = mask[b*Lz + l] ? -INFINITY : fmaf(zp[u], alpha, Shr);
    lmax = fmaxf(lmax, raw[u]);
  }
  float gmax = block_max(lmax, sbuf);
  float e[4]; float lsum = 0.f, lt = 0.f;
#pragma unroll
  for (int u = 0; u < 4; u++) { e[u] = expf(raw[u] - gmax); lsum += e[u]; lt += e[u]*zp[u]; }
  float gsum = block_sum(lsum, sbuf);
  __syncthreads();
  float gt   = block_sum(lt,   sbuf);
  float inv = 1.f / gsum;
#pragma unroll
  for (int u = 0; u < 4; u++) { int l = tid + (u << 8); z[b*Lz + l] = e[u]*inv; }
  float S = gt * inv;
  m_out[b*Dz + tid] = (1.f - S) + hwv * S;
}

// ---------------- final: materialize M and copy final states ----------------
__global__ __launch_bounds__(256,1) void write_final(
  const float* __restrict__ z, const float* __restrict__ hr,
  const float* __restrict__ cr, const float* __restrict__ hw,
  const float* __restrict__ cw, float* __restrict__ out)
{
  __shared__ float sz[128];
  const int b = blockIdx.y;
  const int l0 = blockIdx.x << 7;
  const int tid = threadIdx.x;
  if (tid < 128) sz[tid] = z[b*Lz + l0 + tid];
  __syncthreads();
  float hwv = hw[b*Dz + tid];
  float* Mo = out + 1179648 + ((size_t)b*Lz + l0)*Dz;
  for (int l = 0; l < 128; l++) {
    float zv = sz[l];
    Mo[(size_t)l*Dz + tid] = (1.f - zv) + hwv * zv;
  }
  if (blockIdx.x == 0) {
    int i = b*Dz + tid;
    out[1048576 + i]         = hr[i];
    out[1048576 + 32768 + i] = cr[i];
    out[1048576 + 65536 + i] = hw[i];
    out[1048576 + 98304 + i] = cw[i];
  }
}

// ---------------- init ----------------
__global__ void init_states(const float* __restrict__ hr0, const float* __restrict__ cr0,
                            const float* __restrict__ hw0, const float* __restrict__ cw0)
{
  int i = blockIdx.x*256 + threadIdx.x;
  g_hr[i] = hr0[i];
  g_cr[i] = cr0[i];
  g_hw[i] = hw0[i];
  g_cw[i] = cw0[i];
}

// ---------------- launch ----------------
extern "C" void kernel_launch(void* const* d_in, const int* in_sizes, int n_in,
                              void* d_out, int out_size)
{
  const float* emb   = (const float*)d_in[0];
  const float* hr0   = (const float*)d_in[1];
  const float* cr0   = (const float*)d_in[2];
  const float* hw0   = (const float*)d_in[3];
  const float* cw0   = (const float*)d_in[4];
  const float* M     = (const float*)d_in[5];
  const int*   mask  = (const int*)d_in[6];
  const float* Wih_r = (const float*)d_in[7];
  const float* Whh_r = (const float*)d_in[8];
  const float* bih_r = (const float*)d_in[9];
  const float* bhh_r = (const float*)d_in[10];
  const float* Wc    = (const float*)d_in[11];
  const float* bc    = (const float*)d_in[12];
  const float* Wih_w = (const float*)d_in[13];
  const float* Whh_w = (const float*)d_in[14];
  const float* bih_w = (const float*)d_in[15];
  const float* bhh_w = (const float*)d_in[16];
  float* out = (float*)d_out;

  float *p_hr, *p_hw, *p_cr, *p_cw, *p_m, *p_logits, *p_z;
  cudaGetSymbolAddress((void**)&p_hr, g_hr);
  cudaGetSymbolAddress((void**)&p_hw, g_hw);
  cudaGetSymbolAddress((void**)&p_cr, g_cr);
  cudaGetSymbolAddress((void**)&p_cw, g_cw);
  cudaGetSymbolAddress((void**)&p_m,  g_m);
  cudaGetSymbolAddress((void**)&p_logits, g_logits);
  cudaGetSymbolAddress((void**)&p_z,  g_z);

  init_states<<<128,256>>>(hr0, cr0, hw0, cw0);

  dim3 lstm_grid(16, 8);
  dim3 comp_grid(8, 8);
  dim3 raw_grid(8, Bz);

  for (int t = 0; t < Tz; t++) {
    const int cur = t & 1, nxt = cur ^ 1;
    float* hr_in  = p_hr + cur*BD;
    float* hr_out = p_hr + nxt*BD;
    float* hw_in  = p_hw + cur*BD;
    float* hw_out = p_hw + nxt*BD;

    // read LSTM
    lstm_kernel<<<lstm_grid,256>>>(emb + (size_t)t*BD, hr_in, Wih_r, Whh_r,
                                   bih_r, bhh_r, p_cr, hr_out, p_cr, nullptr, 0);
    // attention
    if (t == 0) {
      attn0_raw<<<raw_grid,256>>>(hr_out, M, p_z);
      attn0_m<<<Bz,256>>>(M, mask, p_z, p_m);
    } else {
      attn_step<<<Bz,256>>>(hr_out, hw_in, mask, p_z, p_m);
    }
    // comp logits
    comp_gemm<<<comp_grid,256>>>(hr_out, p_m, Wc, bc, p_logits);
    // write LSTM (softmax of logits fused), emits outputs[t]
    lstm_kernel<<<lstm_grid,256>>>(p_logits, hw_in, Wih_w, Whh_w,
                                   bih_w, bhh_w, p_cw, hw_out, p_cw,
                                   out + (size_t)t*BD, 1);
  }

  // final states are in buffer 0 (T=32 even)
  dim3 fin_grid(8, Bz);
  write_final<<<fin_grid,256>>>(p_z, p_hr, p_cr, p_hw, p_cw, out);
}

// round 3
// speedup vs baseline: 1.6712x; 1.6712x over previous
#include <cuda_runtime.h>
#include <math.h>

#define Bz 128
#define Lz 1024
#define Dz 256
#define Tz 32
#define BD (Bz*Dz)      /* 32768  */
#define BL (Bz*Lz)      /* 131072 */
#define SAS 516         /* smem row stride (floats), 516%4==0, 516%32==4 */

// ---------------- scratch (device globals; no allocation) ----------------
__device__ float g_hr[2*BD];
__device__ float g_hw[2*BD];
__device__ float g_cr[BD];
__device__ float g_cw[BD];
__device__ float g_m[BD];
__device__ float g_logits[BD];
__device__ float g_z[BL];
__device__ float g_s[2*Bz];

// ---------------- reduction helpers ----------------
__device__ __forceinline__ float warp_sum(float v){
#pragma unroll
  for (int o=16;o;o>>=1) v += __shfl_xor_sync(0xffffffffu,v,o);
  return v;
}
__device__ __forceinline__ float warp_max(float v){
#pragma unroll
  for (int o=16;o;o>>=1) v = fmaxf(v, __shfl_xor_sync(0xffffffffu,v,o));
  return v;
}
__device__ __forceinline__ float block_sum(float v, float* sbuf){
  v = warp_sum(v);
  int lane = threadIdx.x & 31, w = threadIdx.x >> 5;
  __syncthreads();
  if (lane == 0) sbuf[w] = v;
  __syncthreads();
  float r = sbuf[0];
#pragma unroll
  for (int i=1;i<8;i++) r += sbuf[i];
  return r;
}
__device__ __forceinline__ float block_max(float v, float* sbuf){
  v = warp_max(v);
  int lane = threadIdx.x & 31, w = threadIdx.x >> 5;
  __syncthreads();
  if (lane == 0) sbuf[w] = v;
  __syncthreads();
  float r = sbuf[0];
#pragma unroll
  for (int i=1;i<8;i++) r = fmaxf(r, sbuf[i]);
  return r;
}

// ============ fused LSTM cell v2: resident-W GEMM + pointwise ============
// CTA: 16 b x 16 d x 4 gates. 128 threads, thread tile 2b x 4gates.
// grid (16 dblk, 8 bblk) = 128 CTAs. smem: sA[16][512] + sW[64][512], stride 516.
__global__ __launch_bounds__(128,1) void lstm2(
  const float* __restrict__ x, const float* __restrict__ h_in,
  const float* __restrict__ Wih, const float* __restrict__ Whh,
  const float* __restrict__ bih, const float* __restrict__ bhh,
  float* __restrict__ c_io, float* __restrict__ h_out,
  float* __restrict__ out_copy, int softmax_x)
{
  extern __shared__ __align__(16) float smem[];
  float* sA = smem;              // 16*516 floats
  float* sW = smem + 16*SAS;     // 64*516 floats

  const int tid = threadIdx.x;
  const int bb0 = blockIdx.y << 4;
  const int d0  = blockIdx.x << 4;

  // stage A = [x | h_in], rows 16 x 512 (float4 coalesced, conflict-free STS)
  {
    const float4* x4 = (const float4*)x;
    const float4* h4 = (const float4*)h_in;
    float4* sA4 = (float4*)sA;
    for (int idx = tid; idx < 1024; idx += 128) {
      int r = idx >> 6, c = idx & 63;
      sA4[r*129 + c]      = x4[(size_t)(bb0+r)*64 + c];
      sA4[r*129 + 64 + c] = h4[(size_t)(bb0+r)*64 + c];
    }
  }
  // stage W slice: 64 rows (g*16+dd) x 512 k
  {
    const float4* Wi4 = (const float4*)Wih;
    const float4* Wh4 = (const float4*)Whh;
    float4* sW4 = (float4*)sW;
    for (int idx = tid; idx < 8192; idx += 128) {
      int r = idx >> 7, c = idx & 127;
      int j = ((r >> 4) << 8) + d0 + (r & 15);     // g*256 + d0 + dd
      float4 v = (c < 64) ? Wi4[(size_t)j*64 + c] : Wh4[(size_t)j*64 + (c-64)];
      sW4[r*129 + c] = v;
    }
  }
  __syncthreads();

  if (softmax_x) {
    // per-row softmax of x part (k<256). 4 warps x 4 rows, 8 lanes per row.
    int lane = tid & 31, w = tid >> 5;
    int row = (w << 2) + (lane >> 3);
    int sub = lane & 7;
    float* Ar = sA + row*SAS;
    float mx = -INFINITY;
    for (int k = sub; k < 256; k += 8) mx = fmaxf(mx, Ar[k]);
    mx = fmaxf(mx, __shfl_xor_sync(0xffffffffu, mx, 4));
    mx = fmaxf(mx, __shfl_xor_sync(0xffffffffu, mx, 2));
    mx = fmaxf(mx, __shfl_xor_sync(0xffffffffu, mx, 1));
    float sm = 0.f;
    for (int k = sub; k < 256; k += 8) { float e = expf(Ar[k]-mx); Ar[k] = e; sm += e; }
    sm += __shfl_xor_sync(0xffffffffu, sm, 4);
    sm += __shfl_xor_sync(0xffffffffu, sm, 2);
    sm += __shfl_xor_sync(0xffffffffu, sm, 1);
    float inv = 1.f / sm;
    for (int k = sub; k < 256; k += 8) Ar[k] *= inv;
    __syncthreads();
  }

  const int di = tid & 15;
  const int p  = tid >> 4;           // 0..7 -> b = 2p, 2p+1
  const float* a0 = sA + (p*2  )*SAS;
  const float* a1 = sA + (p*2+1)*SAS;

  float ac0[4] = {0.f,0.f,0.f,0.f};
  float ac1[4] = {0.f,0.f,0.f,0.f};
#pragma unroll 4
  for (int k = 0; k < 512; k += 4) {
    float4 A0 = *(const float4*)(a0 + k);
    float4 A1 = *(const float4*)(a1 + k);
#pragma unroll
    for (int g = 0; g < 4; g++) {
      float4 W = *(const float4*)(sW + (g*16 + di)*SAS + k);
      ac0[g] = fmaf(A0.x,W.x, fmaf(A0.y,W.y, fmaf(A0.z,W.z, fmaf(A0.w,W.w, ac0[g]))));
      ac1[g] = fmaf(A1.x,W.x, fmaf(A1.y,W.y, fmaf(A1.z,W.z, fmaf(A1.w,W.w, ac1[g]))));
    }
  }

  const int d = d0 + di;
  float bs0 = bih[d]       + bhh[d];
  float bs1 = bih[256 + d] + bhh[256 + d];
  float bs2 = bih[512 + d] + bhh[512 + d];
  float bs3 = bih[768 + d] + bhh[768 + d];

#pragma unroll
  for (int v = 0; v < 2; v++) {
    float* ac = v ? ac1 : ac0;
    int b = bb0 + p*2 + v;
    int off = b*Dz + d;
    float ig = 1.f/(1.f+expf(-(ac[0]+bs0)));
    float fg = 1.f/(1.f+expf(-(ac[1]+bs1)));
    float gg = tanhf(ac[2]+bs2);
    float og = 1.f/(1.f+expf(-(ac[3]+bs3)));
    float c2 = fmaf(fg, c_io[off], ig*gg);
    c_io[off] = c2;
    float hv = og * tanhf(c2);
    h_out[off] = hv;
    if (out_copy) out_copy[off] = hv;
  }
}

// ============ comp logits GEMM v2: [hr|m] @ Wc^T + bc ============
// CTA: 16 b x 32 j. 128 threads, thread tile 2b x 2j (j = ji, ji+16).
// grid (8 jblk, 8 bblk) = 64 CTAs.
__global__ __launch_bounds__(128,1) void comp2(
  const float* __restrict__ hr, const float* __restrict__ m,
  const float* __restrict__ Wc, const float* __restrict__ bc,
  float* __restrict__ logits)
{
  extern __shared__ __align__(16) float smem[];
  float* sA = smem;              // 16*516
  float* sW = smem + 16*SAS;     // 32*516

  const int tid = threadIdx.x;
  const int bb0 = blockIdx.y << 4;
  const int j0  = blockIdx.x << 5;

  {
    const float4* x4 = (const float4*)hr;
    const float4* m4 = (const float4*)m;
    float4* sA4 = (float4*)sA;
    for (int idx = tid; idx < 1024; idx += 128) {
      int r = idx >> 6, c = idx & 63;
      sA4[r*129 + c]      = x4[(size_t)(bb0+r)*64 + c];
      sA4[r*129 + 64 + c] = m4[(size_t)(bb0+r)*64 + c];
    }
    const float4* W4 = (const float4*)Wc;     // row = 128 float4
    float4* sW4 = (float4*)sW;
    for (int idx = tid; idx < 4096; idx += 128) {
      int r = idx >> 7, c = idx & 127;
      sW4[r*129 + c] = W4[(size_t)(j0+r)*128 + c];
    }
  }
  __syncthreads();

  const int ji = tid & 15;
  const int p  = tid >> 4;
  const float* a0 = sA + (p*2  )*SAS;
  const float* a1 = sA + (p*2+1)*SAS;
  const float* w0 = sW + ji*SAS;
  const float* w1 = sW + (ji+16)*SAS;

  float ac00=0.f, ac01=0.f, ac10=0.f, ac11=0.f;
#pragma unroll 4
  for (int k = 0; k < 512; k += 4) {
    float4 A0 = *(const float4*)(a0 + k);
    float4 A1 = *(const float4*)(a1 + k);
    float4 W0 = *(const float4*)(w0 + k);
    float4 W1 = *(const float4*)(w1 + k);
    ac00 = fmaf(A0.x,W0.x, fmaf(A0.y,W0.y, fmaf(A0.z,W0.z, fmaf(A0.w,W0.w, ac00))));
    ac01 = fmaf(A0.x,W1.x, fmaf(A0.y,W1.y, fmaf(A0.z,W1.z, fmaf(A0.w,W1.w, ac01))));
    ac10 = fmaf(A1.x,W0.x, fmaf(A1.y,W0.y, fmaf(A1.z,W0.z, fmaf(A1.w,W0.w, ac10))));
    ac11 = fmaf(A1.x,W1.x, fmaf(A1.y,W1.y, fmaf(A1.z,W1.z, fmaf(A1.w,W1.w, ac11))));
  }

  float bc0 = bc[j0 + ji], bc1 = bc[j0 + ji + 16];
  int b0r = bb0 + p*2;
  logits[(b0r  )*Dz + j0 + ji]      = ac00 + bc0;
  logits[(b0r  )*Dz + j0 + ji + 16] = ac01 + bc1;
  logits[(b0r+1)*Dz + j0 + ji]      = ac10 + bc0;
  logits[(b0r+1)*Dz + j0 + ji + 16] = ac11 + bc1;
}

// ---------------- t=0 attention: z_raw = hr . M[b,l,:] ----------------
__global__ __launch_bounds__(256,1) void attn0_raw(
  const float* __restrict__ hr, const float* __restrict__ M, float* __restrict__ z)
{
  __shared__ float shr[256];
  const int b = blockIdx.y;
  const int l0 = blockIdx.x << 7;
  const int tid = threadIdx.x;
  shr[tid] = hr[b*Dz + tid];
  __syncthreads();
  const int warp = tid >> 5, lane = tid & 31;
  for (int l = l0 + warp; l < l0 + 128; l += 8) {
    const float* Mr = M + ((size_t)b*Lz + l)*Dz;
    float s = 0.f;
#pragma unroll
    for (int u = 0; u < 8; u++) { int k = lane + (u << 5); s = fmaf(Mr[k], shr[k], s); }
    s = warp_sum(s);
    if (lane == 0) z[b*Lz + l] = s;
  }
}

// ---- t=0: per-b softmax stats (gmax, 1/sum), also zero g_m ----
__global__ __launch_bounds__(256,1) void attn0_stats(
  const int* __restrict__ mask, const float* __restrict__ z,
  float* __restrict__ s_out, float* __restrict__ m_zero)
{
  __shared__ float sbuf[8];
  const int b = blockIdx.x, tid = threadIdx.x;
  m_zero[b*Dz + tid] = 0.f;
  float raw[4]; float lmax = -INFINITY;
#pragma unroll
  for (int u = 0; u < 4; u++) {
    int l = tid + (u << 8);
    raw[u] = mask[b*Lz + l] ? -INFINITY : z[b*Lz + l];
    lmax = fmaxf(lmax, raw[u]);
  }
  float gmax = block_max(lmax, sbuf);
  float lsum = 0.f;
#pragma unroll
  for (int u = 0; u < 4; u++) lsum += expf(raw[u] - gmax);
  __syncthreads();
  float gsum = block_sum(lsum, sbuf);
  if (tid == 0) { s_out[b*2] = gmax; s_out[b*2+1] = 1.f/gsum; }
}

// ---- t=0: normalize z slice + partial m accumulation ----
__global__ __launch_bounds__(256,1) void attn0_scatter(
  const float* __restrict__ M, const int* __restrict__ mask,
  const float* __restrict__ s_in, float* __restrict__ z, float* __restrict__ m_out)
{
  __shared__ float se[128];
  const int b = blockIdx.y;
  const int l0 = blockIdx.x << 7;
  const int tid = threadIdx.x;
  float gmax = s_in[b*2], inv = s_in[b*2+1];
  if (tid < 128) {
    int l = l0 + tid;
    float raw = z[b*Lz + l];
    float e = mask[b*Lz + l] ? 0.f : expf(raw - gmax) * inv;
    z[b*Lz + l] = e;
    se[tid] = e;
  }
  __syncthreads();
  const float* Mb = M + ((size_t)b*Lz + l0)*Dz + tid;
  float a0=0.f, a1=0.f;
#pragma unroll 4
  for (int l = 0; l < 128; l += 2) {
    a0 = fmaf(se[l],   Mb[(size_t)l*Dz],     a0);
    a1 = fmaf(se[l+1], Mb[(size_t)(l+1)*Dz], a1);
  }
  atomicAdd(&m_out[b*Dz + tid], a0 + a1);
}

// ---------------- t>=1 attention via rank-1 structure of M ----------------
__global__ __launch_bounds__(256,1) void attn_step(
  const float* __restrict__ hr, const float* __restrict__ hw_prev,
  const int* __restrict__ mask, float* __restrict__ z, float* __restrict__ m_out)
{
  __shared__ float sbuf[8];
  const int b = blockIdx.x, tid = threadIdx.x;
  float hrv = hr[b*Dz + tid];
  float hwv = hw_prev[b*Dz + tid];
  float Shr  = block_sum(hrv, sbuf);
  __syncthreads();
  float dotv = block_sum(hrv*hwv, sbuf);
  float alpha = dotv - Shr;
  float zp[4], raw[4]; float lmax = -INFINITY;
#pragma unroll
  for (int u = 0; u < 4; u++) {
    int l = tid + (u << 8);
    zp[u] = z[b*Lz + l];
    raw[u] = mask[b*Lz + l] ? -INFINITY : fmaf(zp[u], alpha, Shr);
    lmax = fmaxf(lmax, raw[u]);
  }
  float gmax = block_max(lmax, sbuf);
  float e[4]; float lsum = 0.f, lt = 0.f;
#pragma unroll
  for (int u = 0; u < 4; u++) { e[u] = expf(raw[u] - gmax); lsum += e[u]; lt += e[u]*zp[u]; }
  float gsum = block_sum(lsum, sbuf);
  __syncthreads();
  float gt   = block_sum(lt,   sbuf);
  float inv = 1.f / gsum;
#pragma unroll
  for (int u = 0; u < 4; u++) { int l = tid + (u << 8); z[b*Lz + l] = e[u]*inv; }
  float S = gt * inv;
  m_out[b*Dz + tid] = (1.f - S) + hwv * S;
}

// ---------------- final: materialize M and copy final states ----------------
__global__ __launch_bounds__(256,1) void write_final(
  const float* __restrict__ z, const float* __restrict__ hr,
  const float* __restrict__ cr, const float* __restrict__ hw,
  const float* __restrict__ cw, float* __restrict__ out)
{
  __shared__ float sz[128];
  const int b = blockIdx.y;
  const int l0 = blockIdx.x << 7;
  const int tid = threadIdx.x;
  if (tid < 128) sz[tid] = z[b*Lz + l0 + tid];
  __syncthreads();
  float hwv = hw[b*Dz + tid];
  float* Mo = out + 1179648 + ((size_t)b*Lz + l0)*Dz;
  for (int l = 0; l < 128; l++) {
    float zv = sz[l];
    Mo[(size_t)l*Dz + tid] = (1.f - zv) + hwv * zv;
  }
  if (blockIdx.x == 0) {
    int i = b*Dz + tid;
    out[1048576 + i]         = hr[i];
    out[1048576 + 32768 + i] = cr[i];
    out[1048576 + 65536 + i] = hw[i];
    out[1048576 + 98304 + i] = cw[i];
  }
}

// ---------------- init ----------------
__global__ void init_states(const float* __restrict__ hr0, const float* __restrict__ cr0,
                            const float* __restrict__ hw0, const float* __restrict__ cw0)
{
  int i = blockIdx.x*256 + threadIdx.x;
  g_hr[i] = hr0[i];
  g_cr[i] = cr0[i];
  g_hw[i] = hw0[i];
  g_cw[i] = cw0[i];
}

// ---------------- launch ----------------
extern "C" void kernel_launch(void* const* d_in, const int* in_sizes, int n_in,
                              void* d_out, int out_size)
{
  const float* emb   = (const float*)d_in[0];
  const float* hr0   = (const float*)d_in[1];
  const float* cr0   = (const float*)d_in[2];
  const float* hw0   = (const float*)d_in[3];
  const float* cw0   = (const float*)d_in[4];
  const float* M     = (const float*)d_in[5];
  const int*   mask  = (const int*)d_in[6];
  const float* Wih_r = (const float*)d_in[7];
  const float* Whh_r = (const float*)d_in[8];
  const float* bih_r = (const float*)d_in[9];
  const float* bhh_r = (const float*)d_in[10];
  const float* Wc    = (const float*)d_in[11];
  const float* bc    = (const float*)d_in[12];
  const float* Wih_w = (const float*)d_in[13];
  const float* Whh_w = (const float*)d_in[14];
  const float* bih_w = (const float*)d_in[15];
  const float* bhh_w = (const float*)d_in[16];
  float* out = (float*)d_out;

  float *p_hr, *p_hw, *p_cr, *p_cw, *p_m, *p_logits, *p_z, *p_s;
  cudaGetSymbolAddress((void**)&p_hr, g_hr);
  cudaGetSymbolAddress((void**)&p_hw, g_hw);
  cudaGetSymbolAddress((void**)&p_cr, g_cr);
  cudaGetSymbolAddress((void**)&p_cw, g_cw);
  cudaGetSymbolAddress((void**)&p_m,  g_m);
  cudaGetSymbolAddress((void**)&p_logits, g_logits);
  cudaGetSymbolAddress((void**)&p_z,  g_z);
  cudaGetSymbolAddress((void**)&p_s,  g_s);

  const int lstm_smem = (16 + 64) * SAS * 4;   // 165120 B
  const int comp_smem = (16 + 32) * SAS * 4;   // 99072 B
  cudaFuncSetAttribute(lstm2, cudaFuncAttributeMaxDynamicSharedMemorySize, lstm_smem);
  cudaFuncSetAttribute(comp2, cudaFuncAttributeMaxDynamicSharedMemorySize, comp_smem);

  init_states<<<128,256>>>(hr0, cr0, hw0, cw0);

  dim3 lstm_grid(16, 8);
  dim3 comp_grid(8, 8);
  dim3 slice_grid(8, Bz);

  for (int t = 0; t < Tz; t++) {
    const int cur = t & 1, nxt = cur ^ 1;
    float* hr_in  = p_hr + cur*BD;
    float* hr_out = p_hr + nxt*BD;
    float* hw_in  = p_hw + cur*BD;
    float* hw_out = p_hw + nxt*BD;

    // read LSTM
    lstm2<<<lstm_grid,128,lstm_smem>>>(emb + (size_t)t*BD, hr_in, Wih_r, Whh_r,
                                       bih_r, bhh_r, p_cr, hr_out, nullptr, 0);
    // attention
    if (t == 0) {
      attn0_raw<<<slice_grid,256>>>(hr_out, M, p_z);
      attn0_stats<<<Bz,256>>>(mask, p_z, p_s, p_m);
      attn0_scatter<<<slice_grid,256>>>(M, mask, p_s, p_z, p_m);
    } else {
      attn_step<<<Bz,256>>>(hr_out, hw_in, mask, p_z, p_m);
    }
    // comp logits
    comp2<<<comp_grid,128,comp_smem>>>(hr_out, p_m, Wc, bc, p_logits);
    // write LSTM (softmax of logits fused), emits outputs[t]
    lstm2<<<lstm_grid,128,lstm_smem>>>(p_logits, hw_in, Wih_w, Whh_w,
                                       bih_w, bhh_w, p_cw, hw_out,
                                       out + (size_t)t*BD, 1);
  }

  // final states are in buffer 0 (T=32 even)
  write_final<<<slice_grid,256>>>(p_z, p_hr, p_cr, p_hw, p_cw, out);
}